// round 2
// baseline (speedup 1.0000x reference)
#include <cuda_runtime.h>
#include <cstdint>
#include <cstddef>

// Problem dims
#define NN 16384
#define DD 64
#define MTILE 128
#define KTILE 32
#define NSTAGES 4
#define NKT (NN / KTILE)            // 512 k-tiles

// Smem layout (floats): padded row stride 36 (144B: 16B-aligned, stride%32==4 -> conflict-free frags)
#define ROWSTRIDE 36
#define A_TILE_F (MTILE * ROWSTRIDE)          // 4608 floats
#define B_TILE_F (DD * ROWSTRIDE)             // 2304 floats
#define STAGE_F (A_TILE_F + B_TILE_F)         // 6912 floats = 27648 B
#define SMEM_TOTAL (NSTAGES * STAGE_F * 4)    // 110592 B

// Scratch: Y^T = (X @ W_agg)^T, [DD][NN] fp32 (tf32-rounded + truncation-compensated)
__device__ float g_Yt[(size_t)DD * NN];

// ---------------- helpers ----------------
__device__ __forceinline__ void cp16(void* dst, const void* src) {
    uint32_t d;
    asm("{ .reg .u64 t; cvta.to.shared.u64 t, %1; cvt.u32.u64 %0, t; }" : "=r"(d) : "l"(dst));
    asm volatile("cp.async.cg.shared.global [%0], [%1], 16;" :: "r"(d), "l"(src));
}
#define CP_COMMIT() asm volatile("cp.async.commit_group;" ::: "memory")
#define CP_WAIT(n)  asm volatile("cp.async.wait_group %0;" :: "n"(n) : "memory")

// tf32 mma.sync m16n8k8, row.col, f32 accumulate
__device__ __forceinline__ void mma_tf32(float d[4], const uint32_t a[4], const uint32_t b[2]) {
    asm volatile(
        "mma.sync.aligned.m16n8k8.row.col.f32.tf32.tf32.f32 "
        "{%0,%1,%2,%3}, {%4,%5,%6,%7}, {%8,%9}, {%0,%1,%2,%3};"
        : "+f"(d[0]), "+f"(d[1]), "+f"(d[2]), "+f"(d[3])
        : "r"(a[0]), "r"(a[1]), "r"(a[2]), "r"(a[3]), "r"(b[0]), "r"(b[1]));
}

// ---------------- Kernel 1: Yt = round_tf32( comp * (X @ W_agg)^T ) ----------------
__global__ void __launch_bounds__(128) y_kernel(const float* __restrict__ X,
                                                const float* __restrict__ Wg) {
    __shared__ float Ws[DD * DD];
    const int t = threadIdx.x;
    for (int i = t; i < DD * DD; i += 128) Ws[i] = Wg[i];
    __syncthreads();

    const int row = blockIdx.x * 128 + t;
    float4 xv[16];
    const float4* Xr = (const float4*)(X + (size_t)row * DD);
#pragma unroll
    for (int i = 0; i < 16; ++i) xv[i] = Xr[i];
    const float* xs = (const float*)xv;

    // compensate A-operand tf32 truncation bias (~2^-11 / ln-mean) once, here
    const float comp = 1.00035f;

#pragma unroll
    for (int p = 0; p < 4; ++p) {
        float acc[16];
#pragma unroll
        for (int d = 0; d < 16; ++d) acc[d] = 0.f;
#pragma unroll
        for (int j = 0; j < 64; ++j) {
            const float xj = xs[j];
            const float4* wr = (const float4*)&Ws[j * 64 + p * 16];
            float4 w0 = wr[0], w1 = wr[1], w2 = wr[2], w3 = wr[3];
            acc[0]  += xj * w0.x; acc[1]  += xj * w0.y; acc[2]  += xj * w0.z; acc[3]  += xj * w0.w;
            acc[4]  += xj * w1.x; acc[5]  += xj * w1.y; acc[6]  += xj * w1.z; acc[7]  += xj * w1.w;
            acc[8]  += xj * w2.x; acc[9]  += xj * w2.y; acc[10] += xj * w2.z; acc[11] += xj * w2.w;
            acc[12] += xj * w3.x; acc[13] += xj * w3.y; acc[14] += xj * w3.z; acc[15] += xj * w3.w;
        }
#pragma unroll
        for (int d = 0; d < 16; ++d) {
            float v = acc[d] * comp;
            uint32_t b;
            asm("cvt.rna.tf32.f32 %0, %1;" : "=r"(b) : "f"(v));
            g_Yt[(size_t)(p * 16 + d) * NN + row] = __uint_as_float(b);
        }
    }
}

// ---------------- Kernel 2: main GEMM + fused epilogue ----------------
__device__ __forceinline__ void fill_stage(float* smem, int slot, int kt,
                                           const float* __restrict__ A,
                                           int mbase, int tid) {
    float* st = smem + slot * STAGE_F;
    // A tile: 128 rows x 32 floats = 1024 x 16B chunks, 256 threads -> 4 each
    const char* Ab = (const char*)A + (size_t)mbase * (NN * 4) + (size_t)kt * 128;
#pragma unroll
    for (int i = 0; i < 4; ++i) {
        const int c = tid + 256 * i;
        const int row = c >> 3;
        const int c16 = c & 7;
        cp16((char*)st + row * (ROWSTRIDE * 4) + c16 * 16,
             Ab + (size_t)row * (NN * 4) + c16 * 16);
    }
    // B tile: 64 rows x 32 floats = 512 chunks -> 2 each
    const char* Bb = (const char*)g_Yt + (size_t)kt * 128;
    float* stB = st + A_TILE_F;
#pragma unroll
    for (int i = 0; i < 2; ++i) {
        const int c = tid + 256 * i;
        const int row = c >> 3;
        const int c16 = c & 7;
        cp16((char*)stB + row * (ROWSTRIDE * 4) + c16 * 16,
             Bb + (size_t)row * (NN * 4) + c16 * 16);
    }
    CP_COMMIT();
}

__global__ void __launch_bounds__(256, 1) gcn_main(const float* __restrict__ A,
                                                   const float* __restrict__ X,
                                                   const float* __restrict__ wv,
                                                   float* __restrict__ out) {
    extern __shared__ float smem[];
    const int tid = threadIdx.x;
    const int lane = tid & 31;
    const int wid = tid >> 5;
    const int wm = wid & 3;        // 4 m-groups of 32 rows
    const int wn = wid >> 2;       // 2 n-groups of 32 cols
    const int mbase = blockIdx.x * MTILE;

    // Accumulators: 2 m-steps x 4 n-steps x 4 regs
    float acc[2][4][4];
#pragma unroll
    for (int ms = 0; ms < 2; ++ms)
#pragma unroll
        for (int ns = 0; ns < 4; ++ns)
#pragma unroll
            for (int r = 0; r < 4; ++r) acc[ms][ns][r] = 0.f;

    // Per-thread fragment base offsets (floats)
    const int l4 = lane >> 2;      // 0..7
    const int lm = lane & 3;       // 0..3
    // A: row = wm*32 + ms*16 + l4 (+8), col = ks*8 + lm (+4)
    const int aoff = (wm * 32 + l4) * ROWSTRIDE + lm;
    // B: row(n) = wn*32 + ns*8 + l4, col(k) = ks*8 + lm (+4)
    const int boff = A_TILE_F + (wn * 32 + l4) * ROWSTRIDE + lm;

    // Prologue: fill stages 0..NSTAGES-2
    for (int s = 0; s < NSTAGES - 1; ++s) fill_stage(smem, s, s, A, mbase, tid);

    for (int kt = 0; kt < NKT; ++kt) {
        CP_WAIT(NSTAGES - 2);
        __syncthreads();   // all threads' chunks for stage kt visible; all done reading stage kt-1

        const int nf = kt + NSTAGES - 1;
        if (nf < NKT) fill_stage(smem, nf % NSTAGES, nf, A, mbase, tid);
        else          CP_COMMIT();   // keep wait_group accounting uniform in the tail

        const float* st = smem + (kt % NSTAGES) * STAGE_F;
#pragma unroll
        for (int ks = 0; ks < 4; ++ks) {
            uint32_t afr[2][4];
#pragma unroll
            for (int ms = 0; ms < 2; ++ms) {
                const float* ap = st + aoff + ms * (16 * ROWSTRIDE) + ks * 8;
                afr[ms][0] = __float_as_uint(ap[0]);
                afr[ms][1] = __float_as_uint(ap[8 * ROWSTRIDE]);
                afr[ms][2] = __float_as_uint(ap[4]);
                afr[ms][3] = __float_as_uint(ap[8 * ROWSTRIDE + 4]);
            }
            uint32_t bfr[4][2];
#pragma unroll
            for (int ns = 0; ns < 4; ++ns) {
                const float* bp = st + boff + ns * (8 * ROWSTRIDE) + ks * 8;
                bfr[ns][0] = __float_as_uint(bp[0]);
                bfr[ns][1] = __float_as_uint(bp[4]);
            }
#pragma unroll
            for (int ms = 0; ms < 2; ++ms)
#pragma unroll
                for (int ns = 0; ns < 4; ++ns)
                    mma_tf32(acc[ms][ns], afr[ms], bfr[ns]);
        }
    }

    // Fused epilogue: out = w*relu(acc) + (1-w)*X, straight from registers
#pragma unroll
    for (int ms = 0; ms < 2; ++ms) {
        const int r0 = mbase + wm * 32 + ms * 16 + l4;
        const int r1 = r0 + 8;
        const float w0 = wv[r0], o0 = 1.0f - w0;
        const float w1 = wv[r1], o1 = 1.0f - w1;
#pragma unroll
        for (int ns = 0; ns < 4; ++ns) {
            const int col = wn * 32 + ns * 8 + lm * 2;
            const float2 x0 = *(const float2*)(X + (size_t)r0 * DD + col);
            const float2 x1 = *(const float2*)(X + (size_t)r1 * DD + col);
            float2 v0, v1;
            v0.x = w0 * fmaxf(acc[ms][ns][0], 0.f) + o0 * x0.x;
            v0.y = w0 * fmaxf(acc[ms][ns][1], 0.f) + o0 * x0.y;
            v1.x = w1 * fmaxf(acc[ms][ns][2], 0.f) + o1 * x1.x;
            v1.y = w1 * fmaxf(acc[ms][ns][3], 0.f) + o1 * x1.y;
            *(float2*)(out + (size_t)r0 * DD + col) = v0;
            *(float2*)(out + (size_t)r1 * DD + col) = v1;
        }
    }
}

// ---------------- launch ----------------
extern "C" void kernel_launch(void* const* d_in, const int* in_sizes, int n_in,
                              void* d_out, int out_size) {
    const float* X  = (const float*)d_in[0];
    const float* A  = (const float*)d_in[1];
    const float* wv = (const float*)d_in[2];
    const float* Wg = (const float*)d_in[3];
    float* out = (float*)d_out;

    cudaFuncSetAttribute(gcn_main, cudaFuncAttributeMaxDynamicSharedMemorySize, SMEM_TOTAL);

    y_kernel<<<NN / 128, 128>>>(X, Wg);
    gcn_main<<<NN / MTILE, 256, SMEM_TOTAL>>>(A, X, wv, out);
}

// round 3
// speedup vs baseline: 1.1014x; 1.1014x over previous
#include <cuda_runtime.h>
#include <cstdint>
#include <cstddef>

// Problem dims
#define NN 16384
#define DD 64
#define MTILE 128
#define KTILE 64
#define NSTAGES 3
#define NKT (NN / KTILE)            // 256 k-tiles

// Smem: padded row stride 68 floats (272B; %32 banks == 4 -> conflict-free, 16B aligned)
#define RS 68
#define A_TILE_F (MTILE * RS)                 // 8704 floats
#define B_TILE_F (DD * RS)                    // 4352 floats
#define STAGE_F (A_TILE_F + B_TILE_F)         // 13056 floats = 52224 B
#define STAGE_B (STAGE_F * 4)
#define SMEM_TOTAL (NSTAGES * STAGE_B)        // 156672 B

// Scratch: Y^T = (X @ W_agg)^T, [DD][NN] fp32 (tf32-rounded, truncation-compensated)
__device__ float g_Yt[(size_t)DD * NN];

// ---------------- helpers ----------------
__device__ __forceinline__ uint32_t smem_u32(const void* p) {
    uint32_t a;
    asm("{ .reg .u64 t; cvta.to.shared.u64 t, %1; cvt.u32.u64 %0, t; }" : "=r"(a) : "l"(p));
    return a;
}
__device__ __forceinline__ void cp16(uint32_t dst, const void* src) {
    asm volatile("cp.async.cg.shared.global [%0], [%1], 16;" :: "r"(dst), "l"(src));
}
#define CP_COMMIT() asm volatile("cp.async.commit_group;" ::: "memory")
#define CP_WAIT(n)  asm volatile("cp.async.wait_group %0;" :: "n"(n) : "memory")

__device__ __forceinline__ void ldsm_x4(uint32_t r[4], uint32_t addr) {
    asm volatile("ldmatrix.sync.aligned.m8n8.x4.shared.b16 {%0,%1,%2,%3}, [%4];"
                 : "=r"(r[0]), "=r"(r[1]), "=r"(r[2]), "=r"(r[3]) : "r"(addr));
}

// tf32 mma.sync m16n8k8, row.col, f32 accumulate
__device__ __forceinline__ void mma_tf32(float d[4], const uint32_t a[4],
                                         uint32_t b0, uint32_t b1) {
    asm volatile(
        "mma.sync.aligned.m16n8k8.row.col.f32.tf32.tf32.f32 "
        "{%0,%1,%2,%3}, {%4,%5,%6,%7}, {%8,%9}, {%0,%1,%2,%3};"
        : "+f"(d[0]), "+f"(d[1]), "+f"(d[2]), "+f"(d[3])
        : "r"(a[0]), "r"(a[1]), "r"(a[2]), "r"(a[3]), "r"(b0), "r"(b1));
}

// ---------------- Kernel 1: Yt = round_tf32( comp * (X @ W_agg)^T ) ----------------
__global__ void __launch_bounds__(128) y_kernel(const float* __restrict__ X,
                                                const float* __restrict__ Wg) {
    __shared__ float Ws[DD * DD];
    const int t = threadIdx.x;
    for (int i = t; i < DD * DD; i += 128) Ws[i] = Wg[i];
    __syncthreads();

    const int row = blockIdx.x * 128 + t;
    float4 xv[16];
    const float4* Xr = (const float4*)(X + (size_t)row * DD);
#pragma unroll
    for (int i = 0; i < 16; ++i) xv[i] = Xr[i];
    const float* xs = (const float*)xv;

    const float comp = 1.00035f;   // compensate A-operand tf32 truncation bias

#pragma unroll
    for (int p = 0; p < 4; ++p) {
        float acc[16];
#pragma unroll
        for (int d = 0; d < 16; ++d) acc[d] = 0.f;
#pragma unroll
        for (int j = 0; j < 64; ++j) {
            const float xj = xs[j];
            const float4* wr = (const float4*)&Ws[j * 64 + p * 16];
            float4 w0 = wr[0], w1 = wr[1], w2 = wr[2], w3 = wr[3];
            acc[0]  += xj * w0.x; acc[1]  += xj * w0.y; acc[2]  += xj * w0.z; acc[3]  += xj * w0.w;
            acc[4]  += xj * w1.x; acc[5]  += xj * w1.y; acc[6]  += xj * w1.z; acc[7]  += xj * w1.w;
            acc[8]  += xj * w2.x; acc[9]  += xj * w2.y; acc[10] += xj * w2.z; acc[11] += xj * w2.w;
            acc[12] += xj * w3.x; acc[13] += xj * w3.y; acc[14] += xj * w3.z; acc[15] += xj * w3.w;
        }
#pragma unroll
        for (int d = 0; d < 16; ++d) {
            float v = acc[d] * comp;
            uint32_t b;
            asm("cvt.rna.tf32.f32 %0, %1;" : "=r"(b) : "f"(v));
            g_Yt[(size_t)(p * 16 + d) * NN + row] = __uint_as_float(b);
        }
    }
}

// ---------------- Kernel 2: main GEMM + fused epilogue ----------------
__device__ __forceinline__ void fill_stage(uint32_t sb, int slot, int kt,
                                           const float* __restrict__ A,
                                           int mbase, int tid) {
    const uint32_t st = sb + slot * STAGE_B;
    // A tile: 128 rows x 64 floats = 2048 x 16B chunks, 256 threads -> 8 each
    const char* Ab = (const char*)A + (size_t)mbase * (NN * 4) + (size_t)kt * (KTILE * 4);
#pragma unroll
    for (int i = 0; i < 8; ++i) {
        const int c = tid + 256 * i;
        const int row = c >> 4;
        const int c16 = c & 15;
        cp16(st + row * (RS * 4) + c16 * 16,
             Ab + (size_t)row * (NN * 4) + c16 * 16);
    }
    // B tile: 64 rows x 64 floats = 1024 chunks -> 4 each
    const char* Bb = (const char*)g_Yt + (size_t)kt * (KTILE * 4);
    const uint32_t stB = st + A_TILE_F * 4;
#pragma unroll
    for (int i = 0; i < 4; ++i) {
        const int c = tid + 256 * i;
        const int row = c >> 4;
        const int c16 = c & 15;
        cp16(stB + row * (RS * 4) + c16 * 16,
             Bb + (size_t)row * (NN * 4) + c16 * 16);
    }
    CP_COMMIT();
}

__global__ void __launch_bounds__(256, 1) gcn_main(const float* __restrict__ A,
                                                   const float* __restrict__ X,
                                                   const float* __restrict__ wv,
                                                   float* __restrict__ out) {
    extern __shared__ __align__(16) float smem[];
    const uint32_t sb = smem_u32(smem);
    const int tid = threadIdx.x;
    const int lane = tid & 31;
    const int wid = tid >> 5;
    const int wm = wid & 3;        // 4 m-groups of 32 rows
    const int wn = wid >> 2;       // 2 n-groups of 32 cols
    const int mbase = blockIdx.x * MTILE;

    // Accumulators: 2 m-steps x 4 n-steps x 4 regs
    float acc[2][4][4];
#pragma unroll
    for (int ms = 0; ms < 2; ++ms)
#pragma unroll
        for (int ns = 0; ns < 4; ++ns)
#pragma unroll
            for (int r = 0; r < 4; ++r) acc[ms][ns][r] = 0.f;

    // ldmatrix per-thread row addresses (byte offsets into a stage)
    // A (m16n8k8 A-frag, x4 tiles: [rows0-7|c0-3],[rows8-15|c0-3],[rows0-7|c4-7],[rows8-15|c4-7])
    const uint32_t a_addr0 = sb +
        4u * ((wm * 32 + (lane & 15)) * RS + (lane >> 4) * 4);
    // B (x4 covers two n-steps: [n0-7|k0-3],[n0-7|k4-7],[n8-15|k0-3],[n8-15|k4-7])
    const uint32_t b_addr0 = sb + A_TILE_F * 4 +
        4u * ((wn * 32 + (lane & 7) + ((lane >> 4) << 3)) * RS + ((lane >> 3) & 1) * 4);

    // Prologue: fill stages 0..NSTAGES-2
    for (int s = 0; s < NSTAGES - 1; ++s) fill_stage(sb, s, s, A, mbase, tid);

    int slot = 0;
    for (int kt = 0; kt < NKT; ++kt) {
        CP_WAIT(NSTAGES - 2);
        __syncthreads();   // stage kt visible to all; all done reading stage kt-1

        const int nf = kt + NSTAGES - 1;
        if (nf < NKT) fill_stage(sb, (slot + NSTAGES - 1 >= NSTAGES) ? slot - 1 : slot + NSTAGES - 1, nf, A, mbase, tid);
        else          CP_COMMIT();   // uniform wait_group accounting in the tail

        const uint32_t soff = slot * STAGE_B;
        const uint32_t sa = a_addr0 + soff;
        const uint32_t sbb = b_addr0 + soff;
#pragma unroll
        for (int ks = 0; ks < KTILE / 8; ++ks) {
            uint32_t af[2][4], bf[2][4];
            ldsm_x4(af[0], sa + ks * 32);
            ldsm_x4(af[1], sa + 16 * RS * 4 + ks * 32);
            ldsm_x4(bf[0], sbb + ks * 32);
            ldsm_x4(bf[1], sbb + 16 * RS * 4 + ks * 32);
#pragma unroll
            for (int ms = 0; ms < 2; ++ms) {
                mma_tf32(acc[ms][0], af[ms], bf[0][0], bf[0][1]);
                mma_tf32(acc[ms][1], af[ms], bf[0][2], bf[0][3]);
                mma_tf32(acc[ms][2], af[ms], bf[1][0], bf[1][1]);
                mma_tf32(acc[ms][3], af[ms], bf[1][2], bf[1][3]);
            }
        }
        slot = (slot + 1 == NSTAGES) ? 0 : slot + 1;
    }

    // Fused epilogue: out = w*relu(acc) + (1-w)*X, straight from registers
    const int l4 = lane >> 2;
    const int lm = lane & 3;
#pragma unroll
    for (int ms = 0; ms < 2; ++ms) {
        const int r0 = mbase + wm * 32 + ms * 16 + l4;
        const int r1 = r0 + 8;
        const float w0 = wv[r0], o0 = 1.0f - w0;
        const float w1 = wv[r1], o1 = 1.0f - w1;
#pragma unroll
        for (int ns = 0; ns < 4; ++ns) {
            const int col = wn * 32 + ns * 8 + lm * 2;
            const float2 x0 = *(const float2*)(X + (size_t)r0 * DD + col);
            const float2 x1 = *(const float2*)(X + (size_t)r1 * DD + col);
            float2 v0, v1;
            v0.x = w0 * fmaxf(acc[ms][ns][0], 0.f) + o0 * x0.x;
            v0.y = w0 * fmaxf(acc[ms][ns][1], 0.f) + o0 * x0.y;
            v1.x = w1 * fmaxf(acc[ms][ns][2], 0.f) + o1 * x1.x;
            v1.y = w1 * fmaxf(acc[ms][ns][3], 0.f) + o1 * x1.y;
            *(float2*)(out + (size_t)r0 * DD + col) = v0;
            *(float2*)(out + (size_t)r1 * DD + col) = v1;
        }
    }
}

// ---------------- launch ----------------
extern "C" void kernel_launch(void* const* d_in, const int* in_sizes, int n_in,
                              void* d_out, int out_size) {
    const float* X  = (const float*)d_in[0];
    const float* A  = (const float*)d_in[1];
    const float* wv = (const float*)d_in[2];
    const float* Wg = (const float*)d_in[3];
    float* out = (float*)d_out;

    cudaFuncSetAttribute(gcn_main, cudaFuncAttributeMaxDynamicSharedMemorySize, SMEM_TOTAL);

    y_kernel<<<NN / 128, 128>>>(X, Wg);
    gcn_main<<<NN / MTILE, 256, SMEM_TOTAL>>>(A, X, wv, out);
}

// round 8
// speedup vs baseline: 1.1476x; 1.0420x over previous
#include <cuda_runtime.h>
#include <cstdint>
#include <cstddef>

// Problem dims
#define NN 16384
#define DD 64
#define MTILE 128
#define KTILE 128
#define NSTAGES 2
#define NKT (NN / KTILE)            // 128 k-tiles

// Smem: padded row stride 132 floats (528B; %32 banks == 4 -> conflict-free, 16B aligned)
#define RS 132
#define A_TILE_F (MTILE * RS)                 // 16896 floats
#define B_TILE_F (DD * RS)                    // 8448 floats
#define STAGE_F (A_TILE_F + B_TILE_F)         // 25344 floats = 101376 B
#define STAGE_B (STAGE_F * 4)
#define SMEM_TOTAL (NSTAGES * STAGE_B)        // 202752 B

// Scratch: Y^T = (X @ W_agg)^T, [DD][NN] fp32 (tf32-rounded, truncation-compensated)
__device__ float g_Yt[(size_t)DD * NN];

// ---------------- helpers ----------------
__device__ __forceinline__ uint32_t smem_u32(const void* p) {
    uint32_t a;
    asm("{ .reg .u64 t; cvta.to.shared.u64 t, %1; cvt.u32.u64 %0, t; }" : "=r"(a) : "l"(p));
    return a;
}
__device__ __forceinline__ void cp16(uint32_t dst, const void* src) {
    asm volatile("cp.async.cg.shared.global [%0], [%1], 16;" :: "r"(dst), "l"(src));
}
#define CP_COMMIT() asm volatile("cp.async.commit_group;" ::: "memory")
#define CP_WAIT(n)  asm volatile("cp.async.wait_group %0;" :: "n"(n) : "memory")

__device__ __forceinline__ void ldsm_x4(uint32_t r[4], uint32_t addr) {
    asm volatile("ldmatrix.sync.aligned.m8n8.x4.shared.b16 {%0,%1,%2,%3}, [%4];"
                 : "=r"(r[0]), "=r"(r[1]), "=r"(r[2]), "=r"(r[3]) : "r"(addr));
}

// tf32 mma.sync m16n8k8, row.col, f32 accumulate
__device__ __forceinline__ void mma_tf32(float d[4], const uint32_t a[4],
                                         uint32_t b0, uint32_t b1) {
    asm volatile(
        "mma.sync.aligned.m16n8k8.row.col.f32.tf32.tf32.f32 "
        "{%0,%1,%2,%3}, {%4,%5,%6,%7}, {%8,%9}, {%0,%1,%2,%3};"
        : "+f"(d[0]), "+f"(d[1]), "+f"(d[2]), "+f"(d[3])
        : "r"(a[0]), "r"(a[1]), "r"(a[2]), "r"(a[3]), "r"(b0), "r"(b1));
}

// ---------------- Kernel 1: Yt = round_tf32( comp * (X @ W_agg)^T ) ----------------
__global__ void __launch_bounds__(128) y_kernel(const float* __restrict__ X,
                                                const float* __restrict__ Wg) {
    __shared__ float Ws[DD * DD];
    const int t = threadIdx.x;
    for (int i = t; i < DD * DD; i += 128) Ws[i] = Wg[i];
    __syncthreads();

    const int row = blockIdx.x * 128 + t;
    float4 xv[16];
    const float4* Xr = (const float4*)(X + (size_t)row * DD);
#pragma unroll
    for (int i = 0; i < 16; ++i) xv[i] = Xr[i];
    const float* xs = (const float*)xv;

    const float comp = 1.00035f;   // compensate A-operand tf32 truncation bias

#pragma unroll
    for (int p = 0; p < 4; ++p) {
        float acc[16];
#pragma unroll
        for (int d = 0; d < 16; ++d) acc[d] = 0.f;
#pragma unroll
        for (int j = 0; j < 64; ++j) {
            const float xj = xs[j];
            const float4* wr = (const float4*)&Ws[j * 64 + p * 16];
            float4 w0 = wr[0], w1 = wr[1], w2 = wr[2], w3 = wr[3];
            acc[0]  += xj * w0.x; acc[1]  += xj * w0.y; acc[2]  += xj * w0.z; acc[3]  += xj * w0.w;
            acc[4]  += xj * w1.x; acc[5]  += xj * w1.y; acc[6]  += xj * w1.z; acc[7]  += xj * w1.w;
            acc[8]  += xj * w2.x; acc[9]  += xj * w2.y; acc[10] += xj * w2.z; acc[11] += xj * w2.w;
            acc[12] += xj * w3.x; acc[13] += xj * w3.y; acc[14] += xj * w3.z; acc[15] += xj * w3.w;
        }
#pragma unroll
        for (int d = 0; d < 16; ++d) {
            float v = acc[d] * comp;
            uint32_t b;
            asm("cvt.rna.tf32.f32 %0, %1;" : "=r"(b) : "f"(v));
            g_Yt[(size_t)(p * 16 + d) * NN + row] = __uint_as_float(b);
        }
    }
}

// ---------------- Kernel 2: main GEMM + fused epilogue ----------------
__device__ __forceinline__ void fill_stage(uint32_t sb, int slot, int kt,
                                           const float* __restrict__ A,
                                           int mbase, int tid) {
    const uint32_t st = sb + slot * STAGE_B;
    // A tile: 128 rows x 128 floats = 4096 x 16B chunks, 256 threads -> 16 each
    const char* Ab = (const char*)A + (size_t)mbase * (NN * 4) + (size_t)kt * (KTILE * 4);
#pragma unroll
    for (int i = 0; i < 16; ++i) {
        const int c = tid + 256 * i;
        const int row = c >> 5;
        const int c16 = c & 31;
        cp16(st + row * (RS * 4) + c16 * 16,
             Ab + (size_t)row * (NN * 4) + c16 * 16);
    }
    // B tile: 64 rows x 128 floats = 2048 chunks -> 8 each
    const char* Bb = (const char*)g_Yt + (size_t)kt * (KTILE * 4);
    const uint32_t stB = st + A_TILE_F * 4;
#pragma unroll
    for (int i = 0; i < 8; ++i) {
        const int c = tid + 256 * i;
        const int row = c >> 5;
        const int c16 = c & 31;
        cp16(stB + row * (RS * 4) + c16 * 16,
             Bb + (size_t)row * (NN * 4) + c16 * 16);
    }
    CP_COMMIT();
}

__global__ void __launch_bounds__(256, 1) gcn_main(const float* __restrict__ A,
                                                   const float* __restrict__ X,
                                                   const float* __restrict__ wv,
                                                   float* __restrict__ out) {
    extern __shared__ __align__(16) float smem[];
    const uint32_t sb = smem_u32(smem);
    const int tid = threadIdx.x;
    const int lane = tid & 31;
    const int wid = tid >> 5;
    const int wm = wid & 3;        // 4 m-groups of 32 rows
    const int wn = wid >> 2;       // 2 n-groups of 32 cols
    const int mbase = blockIdx.x * MTILE;

    // Accumulators: 2 m-steps x 4 n-steps x 4 regs
    float acc[2][4][4];
#pragma unroll
    for (int ms = 0; ms < 2; ++ms)
#pragma unroll
        for (int ns = 0; ns < 4; ++ns)
#pragma unroll
            for (int r = 0; r < 4; ++r) acc[ms][ns][r] = 0.f;

    // ldmatrix per-thread base addresses (byte offsets into a stage), layout validated in R2/R3
    const uint32_t a_addr0 = sb +
        4u * ((wm * 32 + (lane & 15)) * RS + (lane >> 4) * 4);
    const uint32_t b_addr0 = sb + A_TILE_F * 4 +
        4u * ((wn * 32 + (lane & 7) + ((lane >> 4) << 3)) * RS + ((lane >> 3) & 1) * 4);

    // Prologue: fill stage 0
    fill_stage(sb, 0, 0, A, mbase, tid);

    int slot = 0;
    for (int kt = 0; kt < NKT; ++kt) {
        CP_WAIT(0);
        __syncthreads();   // stage `slot` ready; all warps done reading stage slot^1

        if (kt + 1 < NKT) fill_stage(sb, slot ^ 1, kt + 1, A, mbase, tid);

        const uint32_t sa = a_addr0 + slot * STAGE_B;
        const uint32_t sbb = b_addr0 + slot * STAGE_B;

        // Double-buffered fragments: LDSM for ks+1 issues before HMMAs for ks
        uint32_t af[2][2][4], bf[2][2][4];
        ldsm_x4(af[0][0], sa);
        ldsm_x4(af[0][1], sa + 16 * RS * 4);
        ldsm_x4(bf[0][0], sbb);
        ldsm_x4(bf[0][1], sbb + 16 * RS * 4);
#pragma unroll
        for (int ks = 0; ks < KTILE / 8; ++ks) {
            const int cur = ks & 1;
            const int nxt = cur ^ 1;
            if (ks + 1 < KTILE / 8) {
                ldsm_x4(af[nxt][0], sa + (ks + 1) * 32);
                ldsm_x4(af[nxt][1], sa + 16 * RS * 4 + (ks + 1) * 32);
                ldsm_x4(bf[nxt][0], sbb + (ks + 1) * 32);
                ldsm_x4(bf[nxt][1], sbb + 16 * RS * 4 + (ks + 1) * 32);
            }
#pragma unroll
            for (int ms = 0; ms < 2; ++ms) {
                mma_tf32(acc[ms][0], af[cur][ms], bf[cur][0][0], bf[cur][0][1]);
                mma_tf32(acc[ms][1], af[cur][ms], bf[cur][0][2], bf[cur][0][3]);
                mma_tf32(acc[ms][2], af[cur][ms], bf[cur][1][0], bf[cur][1][1]);
                mma_tf32(acc[ms][3], af[cur][ms], bf[cur][1][2], bf[cur][1][3]);
            }
        }
        slot ^= 1;
    }

    // Fused epilogue: out = w*relu(acc) + (1-w)*X, straight from registers
    const int l4 = lane >> 2;
    const int lm = lane & 3;
#pragma unroll
    for (int ms = 0; ms < 2; ++ms) {
        const int r0 = mbase + wm * 32 + ms * 16 + l4;
        const int r1 = r0 + 8;
        const float w0 = wv[r0], o0 = 1.0f - w0;
        const float w1 = wv[r1], o1 = 1.0f - w1;
#pragma unroll
        for (int ns = 0; ns < 4; ++ns) {
            const int col = wn * 32 + ns * 8 + lm * 2;
            const float2 x0 = *(const float2*)(X + (size_t)r0 * DD + col);
            const float2 x1 = *(const float2*)(X + (size_t)r1 * DD + col);
            float2 v0, v1;
            v0.x = w0 * fmaxf(acc[ms][ns][0], 0.f) + o0 * x0.x;
            v0.y = w0 * fmaxf(acc[ms][ns][1], 0.f) + o0 * x0.y;
            v1.x = w1 * fmaxf(acc[ms][ns][2], 0.f) + o1 * x1.x;
            v1.y = w1 * fmaxf(acc[ms][ns][3], 0.f) + o1 * x1.y;
            *(float2*)(out + (size_t)r0 * DD + col) = v0;
            *(float2*)(out + (size_t)r1 * DD + col) = v1;
        }
    }
}

// ---------------- launch ----------------
extern "C" void kernel_launch(void* const* d_in, const int* in_sizes, int n_in,
                              void* d_out, int out_size) {
    const float* X  = (const float*)d_in[0];
    const float* A  = (const float*)d_in[1];
    const float* wv = (const float*)d_in[2];
    const float* Wg = (const float*)d_in[3];
    float* out = (float*)d_out;

    cudaFuncSetAttribute(gcn_main, cudaFuncAttributeMaxDynamicSharedMemorySize, SMEM_TOTAL);

    y_kernel<<<NN / 128, 128>>>(X, Wg);
    gcn_main<<<NN / MTILE, 256, SMEM_TOTAL>>>(A, X, wv, out);
}